// round 2
// baseline (speedup 1.0000x reference)
#include <cuda_runtime.h>
#include <cuda_bf16.h>
#include <cstdint>

#define DIM 128
#define NLAYERS 4
#define NQ 7
#define TILE_M 128
#define NTHREADS 256
#define KPAD 136      // bf16 elems per smem row (128 + 8 pad -> conflict-free ldmatrix)
#define XPAD 132      // fp32 elems per smem row

// ---- device globals (no allocation allowed) ----
__device__ float2 g_U[DIM * DIM];             // U[k][j] = amp k of circuit|e_j>
__device__ __nv_bfloat16 g_Whi[DIM * DIM];    // A hi split, [n][k]
__device__ __nv_bfloat16 g_Wlo[DIM * DIM];    // A lo split, [n][k]

__device__ __forceinline__ float2 cmul(float2 a, float2 b) {
    return make_float2(a.x * b.x - a.y * b.y, a.x * b.y + a.y * b.x);
}

// ---------------------------------------------------------------------------
// Kernel 1: build U. One block per basis column j; column lives in smem.
// Qubit q <-> bit (6-q) (axis 1+w of the (2,)*7 reshape is the MSB side).
// ---------------------------------------------------------------------------
__global__ void build_u_kernel(const float* __restrict__ w) {
    __shared__ float2 col[DIM];
    const int j = blockIdx.x;
    const int t = threadIdx.x;  // 128 threads

    col[t] = make_float2(t == j ? 1.f : 0.f, 0.f);
    __syncthreads();

    for (int l = 0; l < NLAYERS; l++) {
        // --- 7 Rot gates ---
        for (int q = 0; q < NQ; q++) {
            const float phi = w[(l * NQ + q) * 3 + 0];
            const float th  = w[(l * NQ + q) * 3 + 1];
            const float om  = w[(l * NQ + q) * 3 + 2];
            float sh, ch; sincosf(0.5f * th, &sh, &ch);
            float sap, cap, sam, cam;
            sincosf(0.5f * (phi + om), &sap, &cap);
            sincosf(0.5f * (phi - om), &sam, &cam);
            // Rot = [[e^{-i(phi+om)/2} c, -e^{i(phi-om)/2} s],
            //        [e^{-i(phi-om)/2} s,  e^{i(phi+om)/2} c]]
            const float2 u00 = make_float2( cap * ch, -sap * ch);
            const float2 u01 = make_float2(-cam * sh, -sam * sh);
            const float2 u10 = make_float2( cam * sh, -sam * sh);
            const float2 u11 = make_float2( cap * ch,  sap * ch);
            const int bit = 1 << (6 - q);
            if (!(t & bit)) {
                const float2 a0 = col[t];
                const float2 a1 = col[t | bit];
                float2 m00 = cmul(u00, a0), m01 = cmul(u01, a1);
                float2 m10 = cmul(u10, a0), m11 = cmul(u11, a1);
                col[t]       = make_float2(m00.x + m01.x, m00.y + m01.y);
                col[t | bit] = make_float2(m10.x + m11.x, m10.y + m11.y);
            }
            __syncthreads();
        }
        // --- CNOT ring, range r, sequential (order matters) ---
        const int r = (l % (NQ - 1)) + 1;
        for (int c = 0; c < NQ; c++) {
            const int tg = (c + r) % NQ;
            const int cb = 1 << (6 - c);
            const int tb = 1 << (6 - tg);
            if ((t & cb) && !(t & tb)) {
                const float2 tmp = col[t];
                col[t] = col[t | tb];
                col[t | tb] = tmp;
            }
            __syncthreads();
        }
    }
    g_U[t * DIM + j] = col[t];
}

// ---------------------------------------------------------------------------
// Kernel 2: A[i][j] = sum_k d_k * (Re U[k][i] Re U[k][j] + Im U[k][i] Im U[k][j])
// d_k = (-1)^(b0 ^ b6). Then bf16 hi/lo split.
// ---------------------------------------------------------------------------
__global__ void build_w_kernel() {
    const int i = blockIdx.x;
    const int j = threadIdx.x;
    float acc = 0.f;
    for (int k = 0; k < DIM; k++) {
        const float dk = (((k >> 6) ^ k) & 1) ? -1.f : 1.f;
        const float2 ui = g_U[k * DIM + i];
        const float2 uj = g_U[k * DIM + j];
        acc += dk * (ui.x * uj.x + ui.y * uj.y);
    }
    const __nv_bfloat16 h = __float2bfloat16(acc);
    const __nv_bfloat16 lo = __float2bfloat16(acc - __bfloat162float(h));
    g_Whi[i * DIM + j] = h;
    g_Wlo[i * DIM + j] = lo;
}

// ---------------------------------------------------------------------------
// Main kernel: per 128-row tile: load X -> (xhi,xlo,xf,s) ; GEMM K=384 via
// mma.sync m16n8k16 bf16 (segments: Ahi*xhi, Ahi*xlo, Alo*xhi) ; epilogue
// out[m] = (sum_n y[m][n]*x[m][n]) / s[m].
// ---------------------------------------------------------------------------
#define SM_ZHI 0
#define SM_ZLO 34816
#define SM_WHI 69632
#define SM_WLO 104448
#define SM_XF  139264
#define SM_S   206848
#define SM_OUT 207360
#define SM_TOTAL 208384

__device__ __forceinline__ void ldsm4(uint32_t& r0, uint32_t& r1, uint32_t& r2,
                                      uint32_t& r3, uint32_t addr) {
    asm volatile("ldmatrix.sync.aligned.m8n8.x4.shared.b16 {%0,%1,%2,%3}, [%4];"
                 : "=r"(r0), "=r"(r1), "=r"(r2), "=r"(r3) : "r"(addr));
}
__device__ __forceinline__ void ldsm2(uint32_t& r0, uint32_t& r1, uint32_t addr) {
    asm volatile("ldmatrix.sync.aligned.m8n8.x2.shared.b16 {%0,%1}, [%2];"
                 : "=r"(r0), "=r"(r1) : "r"(addr));
}
__device__ __forceinline__ void mma16816(float* d, const uint32_t* a, const uint32_t* b) {
    asm volatile(
        "mma.sync.aligned.m16n8k16.row.col.f32.bf16.bf16.f32 "
        "{%0,%1,%2,%3}, {%4,%5,%6,%7}, {%8,%9}, {%0,%1,%2,%3};"
        : "+f"(d[0]), "+f"(d[1]), "+f"(d[2]), "+f"(d[3])
        : "r"(a[0]), "r"(a[1]), "r"(a[2]), "r"(a[3]), "r"(b[0]), "r"(b[1]));
}
__device__ __forceinline__ uint32_t pack2bf(float a, float b) {
    return ((uint32_t)__bfloat16_as_ushort(__float2bfloat16(b)) << 16) |
           (uint32_t)__bfloat16_as_ushort(__float2bfloat16(a));
}

__global__ void __launch_bounds__(NTHREADS, 1)
vqa_main_kernel(const float* __restrict__ x, float* __restrict__ out, int ntiles) {
    extern __shared__ char smem[];
    const uint32_t sbase = (uint32_t)__cvta_generic_to_shared(smem);
    float* xf   = (float*)(smem + SM_XF);
    float* sarr = (float*)(smem + SM_S);
    float* outp = (float*)(smem + SM_OUT);

    const int tid = threadIdx.x;
    const int lane = tid & 31;
    const int wid = tid >> 5;
    const int mi = wid & 3;   // m-stripe (32 rows)
    const int nh = wid >> 2;  // n-half (64 cols)

    // ---- load W (A hi/lo) into padded smem, once per CTA ----
    {
        const uint2* whi_g = (const uint2*)g_Whi;
        const uint2* wlo_g = (const uint2*)g_Wlo;
        for (int idx = tid; idx < DIM * 32; idx += NTHREADS) {
            const int i = idx >> 5, c = idx & 31;  // 4 bf16 per chunk
            *(uint2*)(smem + SM_WHI + i * (KPAD * 2) + c * 8) = whi_g[idx];
            *(uint2*)(smem + SM_WLO + i * (KPAD * 2) + c * 8) = wlo_g[idx];
        }
    }

    // ldmatrix lane base addresses (bytes)
    const uint32_t abase = sbase + SM_ZHI +
        (uint32_t)(((32 * mi + (lane & 15)) * KPAD + 8 * (lane >> 4)) * 2);
    const uint32_t bbase = sbase + SM_WHI +
        (uint32_t)(((64 * nh + (lane & 7)) * KPAD + 8 * ((lane >> 3) & 1)) * 2);

    for (int tile = blockIdx.x; tile < ntiles; tile += gridDim.x) {
        __syncthreads();
        // ---- phase 1: load + convert 128x128 fp32 tile ----
        const float* xt = x + (size_t)tile * (TILE_M * DIM);
        #pragma unroll
        for (int rr = 0; rr < 16; rr++) {
            const int row = wid * 16 + rr;
            const float4 v = *(const float4*)(xt + row * DIM + lane * 4);
            *(float4*)(xf + row * XPAD + lane * 4) = v;
            float ss = v.x * v.x + v.y * v.y + v.z * v.z + v.w * v.w;
            #pragma unroll
            for (int o = 16; o > 0; o >>= 1) ss += __shfl_xor_sync(0xffffffffu, ss, o);
            if (lane == 0) sarr[row] = ss;
            // hi/lo bf16 split
            const float hx = __bfloat162float(__float2bfloat16(v.x));
            const float hy = __bfloat162float(__float2bfloat16(v.y));
            const float hz = __bfloat162float(__float2bfloat16(v.z));
            const float hw = __bfloat162float(__float2bfloat16(v.w));
            const uint2 hv = make_uint2(pack2bf(hx, hy), pack2bf(hz, hw));
            const uint2 lv = make_uint2(pack2bf(v.x - hx, v.y - hy),
                                        pack2bf(v.z - hz, v.w - hw));
            *(uint2*)(smem + SM_ZHI + row * (KPAD * 2) + lane * 8) = hv;
            *(uint2*)(smem + SM_ZLO + row * (KPAD * 2) + lane * 8) = lv;
        }
        __syncthreads();

        // ---- phase 2: GEMM, K = 3 segments x 128 ----
        float d[2][8][4];
        #pragma unroll
        for (int mt = 0; mt < 2; mt++)
            #pragma unroll
            for (int nt = 0; nt < 8; nt++)
                #pragma unroll
                for (int q = 0; q < 4; q++) d[mt][nt][q] = 0.f;

        #pragma unroll
        for (int seg = 0; seg < 3; seg++) {
            const uint32_t zo = (seg == 1) ? (uint32_t)(SM_ZLO - SM_ZHI) : 0u;
            const uint32_t wo = (seg == 2) ? (uint32_t)(SM_WLO - SM_WHI) : 0u;
            #pragma unroll
            for (int kk = 0; kk < 8; kk++) {
                const uint32_t ko = (uint32_t)(kk * 32);  // 16 elems * 2B
                uint32_t a0[4], a1[4];
                ldsm4(a0[0], a0[1], a0[2], a0[3], abase + zo + ko);
                ldsm4(a1[0], a1[1], a1[2], a1[3], abase + zo + ko + 16 * KPAD * 2);
                uint32_t bfr[8][2];
                #pragma unroll
                for (int nt = 0; nt < 8; nt++)
                    ldsm2(bfr[nt][0], bfr[nt][1], bbase + wo + ko + nt * 8 * KPAD * 2);
                #pragma unroll
                for (int nt = 0; nt < 8; nt++) {
                    mma16816(d[0][nt], a0, bfr[nt]);
                    mma16816(d[1][nt], a1, bfr[nt]);
                }
            }
        }

        // ---- phase 3: epilogue — out[m] = (y . x)/s ----
        const int tq = lane & 3;
        const int tr = lane >> 2;
        float racc[4] = {0.f, 0.f, 0.f, 0.f};
        #pragma unroll
        for (int mt = 0; mt < 2; mt++) {
            const int row0 = 32 * mi + 16 * mt + tr;
            const float* x0 = xf + row0 * XPAD;
            const float* x1 = x0 + 8 * XPAD;
            #pragma unroll
            for (int nt = 0; nt < 8; nt++) {
                const int c = 64 * nh + 8 * nt + 2 * tq;
                racc[2 * mt]     += d[mt][nt][0] * x0[c] + d[mt][nt][1] * x0[c + 1];
                racc[2 * mt + 1] += d[mt][nt][2] * x1[c] + d[mt][nt][3] * x1[c + 1];
            }
        }
        #pragma unroll
        for (int q = 0; q < 4; q++) {
            racc[q] += __shfl_xor_sync(0xffffffffu, racc[q], 1);
            racc[q] += __shfl_xor_sync(0xffffffffu, racc[q], 2);
        }
        if (tq == 0) {
            #pragma unroll
            for (int q = 0; q < 4; q++) {
                const int row = 32 * mi + 8 * q + tr;
                outp[row * 2 + nh] = racc[q];
            }
        }
        __syncthreads();
        if (tid < TILE_M) {
            out[(size_t)tile * TILE_M + tid] =
                (outp[tid * 2] + outp[tid * 2 + 1]) / sarr[tid];
        }
    }
}

// ---------------------------------------------------------------------------
extern "C" void kernel_launch(void* const* d_in, const int* in_sizes, int n_in,
                              void* d_out, int out_size) {
    const float* x = (const float*)d_in[0];
    const float* w = (const float*)d_in[1];
    float* out = (float*)d_out;

    cudaFuncSetAttribute(vqa_main_kernel,
                         cudaFuncAttributeMaxDynamicSharedMemorySize, SM_TOTAL);

    build_u_kernel<<<DIM, DIM>>>(w);
    build_w_kernel<<<DIM, DIM>>>();

    const int rows = in_sizes[0] / DIM;
    const int ntiles = rows / TILE_M;
    vqa_main_kernel<<<152, NTHREADS, SM_TOTAL>>>(x, out, ntiles);
}